// round 1
// baseline (speedup 1.0000x reference)
#include <cuda_runtime.h>

#define NN 100000
#define NE 3200000
#define FIN 128
#define HH1 64
#define HH2 32
#define NCLS 32

// ---------------- device scratch (no allocations allowed) ----------------
__device__ int   g_deg[NN];
__device__ float g_dinv[NN];
__device__ int   g_rowptr[NN + 1];
__device__ int   g_fill[NN];
__device__ int   g_bsum[256];
__device__ int   g_src[NE];
__device__ float g_h1[(size_t)NN * HH1];   // (x@W1)*dinv[row]
__device__ float g_o1[(size_t)NN * HH1];   // relu'd conv1 output
__device__ float g_h2[(size_t)NN * HH2];   // (o1@W2)*dinv[row]
__device__ float g_o2[(size_t)NN * HH2];   // conv2 output
__device__ int   g_is64;

// ---------------- dtype detection: int64 vs int32 edge_index ----------------
__global__ void k_detect(const long long* __restrict__ p) {
    if (threadIdx.x == 0) {
        int ok = 1;
        for (int i = 0; i < 16; i++) {
            long long v = p[i];
            if (v < 0 || v >= NN) ok = 0;
        }
        g_is64 = ok;
    }
}

// ---------------- degree count ----------------
__global__ void k_zero() {
    int i = blockIdx.x * blockDim.x + threadIdx.x;
    if (i < NN) g_deg[i] = 0;
}

__global__ void k_count(const long long* __restrict__ d64, const int* __restrict__ d32) {
    int is64 = g_is64;
    for (int e = blockIdx.x * blockDim.x + threadIdx.x; e < NE; e += gridDim.x * blockDim.x) {
        int d = is64 ? (int)d64[e] : d32[e];
        atomicAdd(&g_deg[d], 1);
    }
}

// ---------------- prefix scan (3 kernels) ----------------
__global__ void k_scan1() {
    __shared__ int s[1024];
    int gid = blockIdx.x * 1024 + threadIdx.x;
    int v = (gid < NN) ? g_deg[gid] : 0;
    s[threadIdx.x] = v;
    __syncthreads();
    for (int off = 1; off < 1024; off <<= 1) {
        int t = (threadIdx.x >= off) ? s[threadIdx.x - off] : 0;
        __syncthreads();
        s[threadIdx.x] += t;
        __syncthreads();
    }
    if (gid < NN) g_rowptr[gid + 1] = s[threadIdx.x];
    if (threadIdx.x == 1023) g_bsum[blockIdx.x] = s[1023];
}

__global__ void k_scan2(int nb) {
    if (threadIdx.x == 0) {
        int run = 0;
        for (int b = 0; b < nb; b++) { int t = g_bsum[b]; g_bsum[b] = run; run += t; }
    }
}

__global__ void k_scan3() {
    int gid = blockIdx.x * blockDim.x + threadIdx.x;
    if (gid < NN) {
        g_rowptr[gid + 1] += g_bsum[gid >> 10];
        g_dinv[gid] = rsqrtf((float)(g_deg[gid] + 1));  // +1 self loop
        if (gid == 0) g_rowptr[0] = 0;
    }
}

__global__ void k_fillinit() {
    int gid = blockIdx.x * blockDim.x + threadIdx.x;
    if (gid < NN) g_fill[gid] = g_rowptr[gid];
}

__global__ void k_fill(const long long* __restrict__ s64, const long long* __restrict__ d64,
                       const int* __restrict__ s32, const int* __restrict__ d32) {
    int is64 = g_is64;
    for (int e = blockIdx.x * blockDim.x + threadIdx.x; e < NE; e += gridDim.x * blockDim.x) {
        int s = is64 ? (int)s64[e] : s32[e];
        int d = is64 ? (int)d64[e] : d32[e];
        int pos = atomicAdd(&g_fill[d], 1);
        g_src[pos] = s;
    }
}

// ---------------- GEMM1: h1 = (x @ W1) * dinv[row] ----------------
// block: 256 thr = 8 warps, each warp 4 nodes; W1 in smem as paired float2.
__global__ void k_gemm1(const float* __restrict__ x, const float* __restrict__ W1) {
    __shared__ float2 ws[FIN * 32];  // [k][lane] = (W1[k][lane], W1[k][lane+32]) -> 32KB
    int tid = threadIdx.x;
    for (int i = tid; i < FIN * 32; i += 256) {
        int k = i >> 5, l = i & 31;
        ws[i] = make_float2(W1[k * HH1 + l], W1[k * HH1 + l + 32]);
    }
    __syncthreads();
    int warp = tid >> 5, lane = tid & 31;
    int nb = blockIdx.x * 32 + warp * 4;  // NN % 32 == 0
    float xr[4][4];
#pragma unroll
    for (int i = 0; i < 4; i++) {
        const float* row = x + (size_t)(nb + i) * FIN;
#pragma unroll
        for (int j = 0; j < 4; j++) xr[i][j] = row[lane + 32 * j];
    }
    float2 acc[4] = {{0,0},{0,0},{0,0},{0,0}};
#pragma unroll
    for (int j = 0; j < 4; j++) {
#pragma unroll
        for (int kk = 0; kk < 32; kk++) {
            float2 w = ws[((j << 5) + kk) * 32 + lane];
#pragma unroll
            for (int i = 0; i < 4; i++) {
                float xv = __shfl_sync(0xffffffffu, xr[i][j], kk);
                acc[i].x += xv * w.x;
                acc[i].y += xv * w.y;
            }
        }
    }
#pragma unroll
    for (int i = 0; i < 4; i++) {
        float di = g_dinv[nb + i];
        g_h1[(size_t)(nb + i) * HH1 + lane]      = acc[i].x * di;
        g_h1[(size_t)(nb + i) * HH1 + lane + 32] = acc[i].y * di;
    }
}

// ---------------- gather (64 feat): o1 = relu(dinv*(sum + self) + b1) ----------------
__global__ void k_gather64(const float* __restrict__ b1) {
    int lane = threadIdx.x & 31;
    int w  = (blockIdx.x * blockDim.x + threadIdx.x) >> 5;
    int nw = (gridDim.x * blockDim.x) >> 5;
    const float2* hp = (const float2*)g_h1;
    float bx = b1[2 * lane], by = b1[2 * lane + 1];
    for (int n = w; n < NN; n += nw) {
        int beg = g_rowptr[n], end = g_rowptr[n + 1];
        float ax = 0.f, ay = 0.f;
        int e = beg;
        for (; e + 4 <= end; e += 4) {
            int s0 = g_src[e], s1 = g_src[e + 1], s2 = g_src[e + 2], s3 = g_src[e + 3];
            float2 v0 = hp[s0 * 32 + lane];
            float2 v1 = hp[s1 * 32 + lane];
            float2 v2 = hp[s2 * 32 + lane];
            float2 v3 = hp[s3 * 32 + lane];
            ax += v0.x + v1.x + v2.x + v3.x;
            ay += v0.y + v1.y + v2.y + v3.y;
        }
        for (; e < end; ++e) {
            int s = g_src[e];
            float2 v = hp[s * 32 + lane];
            ax += v.x; ay += v.y;
        }
        float2 sf = hp[n * 32 + lane];
        float di = g_dinv[n];
        float o0 = di * (ax + sf.x) + bx;
        float o1 = di * (ay + sf.y) + by;
        float2 ov = make_float2(o0 > 0.f ? o0 : 0.f, o1 > 0.f ? o1 : 0.f);
        ((float2*)g_o1)[n * 32 + lane] = ov;
    }
}

// ---------------- GEMM2: h2 = (o1 @ W2) * dinv[row] ----------------
__global__ void k_gemm2(const float* __restrict__ W2) {
    __shared__ float ws[HH1 * HH2];  // 8KB
    int tid = threadIdx.x;
    for (int i = tid; i < HH1 * HH2; i += 256) ws[i] = W2[i];
    __syncthreads();
    int warp = tid >> 5, lane = tid & 31;
    int nb = blockIdx.x * 32 + warp * 4;
    float xr[4][2];
#pragma unroll
    for (int i = 0; i < 4; i++) {
        const float* row = g_o1 + (size_t)(nb + i) * HH1;
        xr[i][0] = row[lane];
        xr[i][1] = row[lane + 32];
    }
    float acc[4] = {0.f, 0.f, 0.f, 0.f};
#pragma unroll
    for (int j = 0; j < 2; j++) {
#pragma unroll
        for (int kk = 0; kk < 32; kk++) {
            float wv = ws[((j << 5) + kk) * HH2 + lane];
#pragma unroll
            for (int i = 0; i < 4; i++) {
                float xv = __shfl_sync(0xffffffffu, xr[i][j], kk);
                acc[i] += xv * wv;
            }
        }
    }
#pragma unroll
    for (int i = 0; i < 4; i++) {
        g_h2[(size_t)(nb + i) * HH2 + lane] = acc[i] * g_dinv[nb + i];
    }
}

// ---------------- gather (32 feat): o2 = dinv*(sum + self) + b2 (no relu) ----------------
__global__ void k_gather32(const float* __restrict__ b2) {
    int lane = threadIdx.x & 31;
    int w  = (blockIdx.x * blockDim.x + threadIdx.x) >> 5;
    int nw = (gridDim.x * blockDim.x) >> 5;
    float bv = b2[lane];
    for (int n = w; n < NN; n += nw) {
        int beg = g_rowptr[n], end = g_rowptr[n + 1];
        float a = 0.f;
        int e = beg;
        for (; e + 4 <= end; e += 4) {
            int s0 = g_src[e], s1 = g_src[e + 1], s2 = g_src[e + 2], s3 = g_src[e + 3];
            float v0 = g_h2[s0 * 32 + lane];
            float v1 = g_h2[s1 * 32 + lane];
            float v2 = g_h2[s2 * 32 + lane];
            float v3 = g_h2[s3 * 32 + lane];
            a += v0 + v1 + v2 + v3;
        }
        for (; e < end; ++e) a += g_h2[g_src[e] * 32 + lane];
        float di = g_dinv[n];
        g_o2[n * 32 + lane] = di * (a + g_h2[n * 32 + lane]) + bv;
    }
}

// ---------------- final: out = relu(o2 @ Wf + bf) @ Wo + bo ----------------
__global__ void k_final(const float* __restrict__ Wf, const float* __restrict__ bf,
                        const float* __restrict__ Wo, const float* __restrict__ bo,
                        float* __restrict__ out) {
    __shared__ float wfs[32 * 32], wos[32 * 32], bfs[32], bos[32];
    int tid = threadIdx.x;
    for (int i = tid; i < 1024; i += 256) { wfs[i] = Wf[i]; wos[i] = Wo[i]; }
    if (tid < 32) { bfs[tid] = bf[tid]; bos[tid] = bo[tid]; }
    __syncthreads();
    int warp = tid >> 5, lane = tid & 31;
    int nb = blockIdx.x * 32 + warp * 4;
    float r[4], h3[4], a1[4], a2[4];
#pragma unroll
    for (int i = 0; i < 4; i++) {
        r[i]  = g_o2[(size_t)(nb + i) * 32 + lane];
        a1[i] = bfs[lane];
    }
#pragma unroll
    for (int kk = 0; kk < 32; kk++) {
        float wv = wfs[kk * 32 + lane];
#pragma unroll
        for (int i = 0; i < 4; i++)
            a1[i] += __shfl_sync(0xffffffffu, r[i], kk) * wv;
    }
#pragma unroll
    for (int i = 0; i < 4; i++) {
        h3[i] = a1[i] > 0.f ? a1[i] : 0.f;
        a2[i] = bos[lane];
    }
#pragma unroll
    for (int kk = 0; kk < 32; kk++) {
        float wv = wos[kk * 32 + lane];
#pragma unroll
        for (int i = 0; i < 4; i++)
            a2[i] += __shfl_sync(0xffffffffu, h3[i], kk) * wv;
    }
#pragma unroll
    for (int i = 0; i < 4; i++)
        out[(size_t)(nb + i) * 32 + lane] = a2[i];
}

// ---------------- launch ----------------
extern "C" void kernel_launch(void* const* d_in, const int* in_sizes, int n_in,
                              void* d_out, int out_size) {
    const float*     x  = (const float*)d_in[0];
    const long long* ei = (const long long*)d_in[1];
    const int*       ei32 = (const int*)d_in[1];
    const float* W1 = (const float*)d_in[2];
    const float* b1 = (const float*)d_in[3];
    const float* W2 = (const float*)d_in[4];
    const float* b2 = (const float*)d_in[5];
    const float* Wf = (const float*)d_in[6];
    const float* bf = (const float*)d_in[7];
    const float* Wo = (const float*)d_in[8];
    const float* bo = (const float*)d_in[9];
    float* out = (float*)d_out;

    const long long* s64 = ei;
    const long long* d64 = ei + NE;
    const int*       s32 = ei32;
    const int*       d32 = ei32 + NE;

    int nScanBlocks = (NN + 1023) / 1024;

    k_detect<<<1, 32>>>(ei);
    k_zero<<<(NN + 511) / 512, 512>>>();
    k_count<<<4096, 256>>>(d64, d32);
    k_scan1<<<nScanBlocks, 1024>>>();
    k_scan2<<<1, 32>>>(nScanBlocks);
    k_scan3<<<(NN + 511) / 512, 512>>>();
    k_fillinit<<<(NN + 511) / 512, 512>>>();
    k_fill<<<4096, 256>>>(s64, d64, s32, d32);
    k_gemm1<<<NN / 32, 256>>>(x, W1);
    k_gather64<<<2048, 256>>>(b1);
    k_gemm2<<<NN / 32, 256>>>(W2);
    k_gather32<<<2048, 256>>>(b2);
    k_final<<<NN / 32, 256>>>(Wf, bf, Wo, bo, out);
}